// round 13
// baseline (speedup 1.0000x reference)
#include <cuda_runtime.h>
#include <cuda_bf16.h>
#include <math.h>
#include <stdint.h>

#define NTOT   8192
#define BHALF  4096
#define DDIM   256
#define MT     128                  // rows per tile-block
#define CT     128                  // cols per tile
#define NRB    (NTOT / MT)          // 64 row-blocks
#define AS8    272                  // smem row stride bytes (256 data + 16 pad)
#define TILE8  (MT * AS8)           // 34816 bytes per tile buffer
#define NUNITS 2080                 // 32 strip-pairs x 65 tiles = all upper-tri tiles
#define NCTA   296                  // 2 CTAs x 148 SMs, persistent
#define THREADS 512

// Scratch: int8-quantized normalized vectors (q = round(127*zhat)),
// per-row sum-exp, per-row positive logit, work counter + completion ticket
__device__ int8_t g_q[NTOT * DDIM];
__device__ float g_rowsum[NTOT];
__device__ float g_pos[NTOT];
__device__ unsigned g_unit;
__device__ unsigned g_ticket;

// ---------------------------------------------------------------------------
__device__ __forceinline__ uint32_t smem_u32(const void* p) {
    uint32_t a;
    asm("{ .reg .u64 t; cvta.to.shared.u64 t, %1; cvt.u32.u64 %0, t; }"
        : "=r"(a) : "l"(p));
    return a;
}
__device__ __forceinline__ float ex2f(float x) {     // 2^x on MUFU pipe
    float r;
    asm("ex2.approx.f32 %0, %1;" : "=f"(r) : "f"(x));
    return r;
}
#define CP_ASYNC16(dst, src) \
    asm volatile("cp.async.cg.shared.global [%0], [%1], 16;" :: "r"(dst), "l"(src))
#define CP_COMMIT() asm volatile("cp.async.commit_group;" ::: "memory")
#define CP_WAIT(n)  asm volatile("cp.async.wait_group %0;" :: "n"(n) : "memory")

#define LDSM_X4(r0, r1, r2, r3, a)                                        \
    asm volatile("ldmatrix.sync.aligned.m8n8.x4.shared.b16 {%0,%1,%2,%3}, [%4];" \
        : "=r"(r0), "=r"(r1), "=r"(r2), "=r"(r3) : "r"(a))

#define MMAS8(d, a0, a1, a2, a3, b0, b1)                                  \
    asm volatile("mma.sync.aligned.m16n8k32.row.col.s32.s8.s8.s32 "       \
        "{%0,%1,%2,%3}, {%4,%5,%6,%7}, {%8,%9}, {%0,%1,%2,%3};"           \
        : "+r"((d)[0]), "+r"((d)[1]), "+r"((d)[2]), "+r"((d)[3])          \
        : "r"(a0), "r"(a1), "r"(a2), "r"(a3), "r"(b0), "r"(b1))

// First K-step: C operand is the broadcast MAGI constant -> no acc init MOVs.
#define MMAS8_INIT(d, a0, a1, a2, a3, b0, b1, c)                          \
    asm volatile("mma.sync.aligned.m16n8k32.row.col.s32.s8.s8.s32 "       \
        "{%0,%1,%2,%3}, {%4,%5,%6,%7}, {%8,%9}, {%10,%10,%10,%10};"       \
        : "=r"((d)[0]), "=r"((d)[1]), "=r"((d)[2]), "=r"((d)[3])          \
        : "r"(a0), "r"(a1), "r"(a2), "r"(a3), "r"(b0), "r"(b1), "r"(c))

// ---------------------------------------------------------------------------
// Prep: each warp handles 4 rows; also zeroes g_rowsum / g_unit / g_ticket.
// ---------------------------------------------------------------------------
__device__ __forceinline__ const float* row_ptr(int row,
        const float* zi, const float* zj) {
    return (row < BHALF) ? (zi + (size_t)row * DDIM)
                         : (zj + (size_t)(row - BHALF) * DDIM);
}
__device__ __forceinline__ void quant_store(int row, float sc,
        float4 v0, float4 v1, int lane) {
    int q0 = __float2int_rn(v0.x * sc), q1 = __float2int_rn(v0.y * sc);
    int q2 = __float2int_rn(v0.z * sc), q3 = __float2int_rn(v0.w * sc);
    int q4 = __float2int_rn(v1.x * sc), q5 = __float2int_rn(v1.y * sc);
    int q6 = __float2int_rn(v1.z * sc), q7 = __float2int_rn(v1.w * sc);
    uint2 pk;
    pk.x = (q0 & 0xff) | ((q1 & 0xff) << 8) | ((q2 & 0xff) << 16) | (q3 << 24);
    pk.y = (q4 & 0xff) | ((q5 & 0xff) << 8) | ((q6 & 0xff) << 16) | (q7 << 24);
    *(uint2*)(g_q + (size_t)row * DDIM + lane * 8) = pk;
}

__global__ void k_prep(const float* __restrict__ zi, const float* __restrict__ zj) {
    if (blockIdx.x < 32) g_rowsum[blockIdx.x * 256 + threadIdx.x] = 0.0f;
    if (blockIdx.x == 0 && threadIdx.x == 0) { g_unit = 0u; g_ticket = 0u; }

    const int warp = threadIdx.x >> 5;
    const int lane = threadIdx.x & 31;
    const int r0 = blockIdx.x * 32 + warp * 4;

    float4 v[8];
    #pragma unroll
    for (int r = 0; r < 4; r++) {
        const float* s = row_ptr(r0 + r, zi, zj);
        v[2*r]   = ((const float4*)s)[lane * 2 + 0];
        v[2*r+1] = ((const float4*)s)[lane * 2 + 1];
    }
    float ss[4];
    #pragma unroll
    for (int r = 0; r < 4; r++) {
        float4 a = v[2*r], b = v[2*r+1];
        ss[r] = a.x*a.x + a.y*a.y + a.z*a.z + a.w*a.w
              + b.x*b.x + b.y*b.y + b.z*b.z + b.w*b.w;
    }
    #pragma unroll
    for (int o = 16; o; o >>= 1)
        #pragma unroll
        for (int r = 0; r < 4; r++)
            ss[r] += __shfl_xor_sync(0xffffffffu, ss[r], o);
    #pragma unroll
    for (int r = 0; r < 4; r++)
        quant_store(r0 + r, 127.0f * rsqrtf(ss[r]), v[2*r], v[2*r+1], lane);
}

// ---------------------------------------------------------------------------
// Async tile loader: 128 rows x 256 int8; 2048 16B chunks over 512 threads.
// ---------------------------------------------------------------------------
__device__ __forceinline__ void load_tile_async(uint32_t dst, int grow0) {
    const int tid = threadIdx.x;
    #pragma unroll
    for (int i = 0; i < 4; i++) {
        int c   = tid + i * THREADS;
        int r   = c >> 4;
        int off = (c & 15) * 16;
        CP_ASYNC16(dst + r * AS8 + off,
                   (const char*)g_q + (size_t)(grow0 + r) * 256 + off);
    }
}

// Decode unit u -> (I, J) on the strip-pair sweep (p = u/65, t = u%65).
__device__ __forceinline__ void decode_unit(unsigned u, int& I, int& J) {
    int p = (int)(u / 65u);
    int t = (int)(u - (unsigned)p * 65u);
    int len1 = NRB - p;                  // tiles in strip I=p (J=p..63)
    I = (t < len1) ? p : (NRB - 1 - p);
    J = (t < len1) ? (p + t) : ((NRB - 1 - p) + (t - len1));
}

// ---------------------------------------------------------------------------
// Main: upper-triangle tile sweep with symmetry, int8 mma m16n8k32.
// R13: persistent CTAs + dynamic work-stealing over a global unit counter
// (fixes the 7-vs-8 chunk quantization tail of the static schedule); the
// next unit is grabbed one iteration ahead and its B tile prefetched during
// the current tile's compute. Ordered units keep A reuse. First-ks MMA uses
// a constant MAGI C operand (no accumulator-init MOVs).
// ---------------------------------------------------------------------------
__global__ void __launch_bounds__(THREADS, 2) k_main(float* out) {
    extern __shared__ char sm[];
    __shared__ unsigned s_u[2];
    __shared__ unsigned s_last;
    __shared__ float red[16];
    const uint32_t sA  = smem_u32(sm);
    const uint32_t sB0 = sA + TILE8;

    const int tid  = threadIdx.x;
    const int lane = tid & 31;
    const int warp = tid >> 5;
    const int wm   = warp & 3;             // M subtile (32 rows)
    const int wn   = warp >> 2;            // N subtile (32 cols), 0..3
    const int l4   = lane >> 2;
    const int lm   = lane & 3;

    // ldmatrix per-lane base offsets (bytes); k-step adds ks*32
    uint32_t aoff[2];
    #pragma unroll
    for (int m = 0; m < 2; m++) {
        int arow = wm * 32 + m * 16 + (lane & 15);
        aoff[m] = sA + (uint32_t)arow * AS8 + (uint32_t)(lane >> 4) * 16;
    }
    uint32_t boff[2];
    #pragma unroll
    for (int nb = 0; nb < 2; nb++) {
        int brow = wn * 32 + nb * 16 + (lane & 7) + ((lane >> 4) << 3);
        boff[nb] = (uint32_t)brow * AS8 + (uint32_t)((lane >> 3) & 1) * 16;
    }

    // exp(cos/T) = 2^(dot_i32 * KQ);  KQ = log2(e)/(T*127^2)
    const float KQ   = 2.8853900817779268f / 16129.0f;
    const float KP   = 2.0f / 16129.0f;
    const float MAGF = 12582912.0f;               // 1.5 * 2^23
    const int   MAGI = 0x4B400000;
    const float BQ   = -MAGF * KQ;
    const float BP   = -MAGF * KP;
    float rs[2][2] = {{0.f, 0.f}, {0.f, 0.f}};

    // ---- prologue: grab first unit, load its A + B ----
    if (tid == 0) s_u[0] = atomicAdd(&g_unit, 1u);
    __syncthreads();
    unsigned u_cur = s_u[0];
    int curI = -1;
    bool worked = false;

    if (u_cur < NUNITS) {
        int I0, J0;
        decode_unit(u_cur, I0, J0);
        curI = I0;
        load_tile_async(sA, I0 * MT);
        load_tile_async(sB0, J0 * CT);
        CP_COMMIT();
        worked = true;

        int it = 0;                        // iteration parity -> B buffer
        for (;;) {
            int I, J;
            decode_unit(u_cur, I, J);
            const uint32_t bufc = sB0 + (uint32_t)(it & 1) * TILE8;

            CP_WAIT(0);                    // B(u_cur) (+A after switch) arrived
            if (tid == 0) s_u[(it + 1) & 1] = atomicAdd(&g_unit, 1u);
            __syncthreads();               // publish B + retire old buf + s_u
            const unsigned u_nxt = s_u[(it + 1) & 1];
            const bool haveNext = (u_nxt < NUNITS);
            int In = 0, Jn = 0;
            if (haveNext) {
                decode_unit(u_nxt, In, Jn);
                load_tile_async(sB0 + (uint32_t)((it + 1) & 1) * TILE8, Jn * CT);
                CP_COMMIT();
            }

            // ---- mainloop: ks=0 seeds acc with MAGI via C operand ----
            int acc[2][4][4];
            {
                uint32_t a[2][4], b[2][4];
                LDSM_X4(a[0][0], a[0][1], a[0][2], a[0][3], aoff[0]);
                LDSM_X4(a[1][0], a[1][1], a[1][2], a[1][3], aoff[1]);
                LDSM_X4(b[0][0], b[0][1], b[0][2], b[0][3], bufc + boff[0]);
                LDSM_X4(b[1][0], b[1][1], b[1][2], b[1][3], bufc + boff[1]);
                #pragma unroll
                for (int m = 0; m < 2; m++)
                    #pragma unroll
                    for (int nb = 0; nb < 2; nb++) {
                        MMAS8_INIT(acc[m][nb*2+0], a[m][0], a[m][1], a[m][2], a[m][3],
                                   b[nb][0], b[nb][1], MAGI);
                        MMAS8_INIT(acc[m][nb*2+1], a[m][0], a[m][1], a[m][2], a[m][3],
                                   b[nb][2], b[nb][3], MAGI);
                    }
            }
            #pragma unroll
            for (int ks = 1; ks < 8; ks++) {
                const uint32_t kb = (uint32_t)ks * 32;
                uint32_t a[2][4], b[2][4];
                LDSM_X4(a[0][0], a[0][1], a[0][2], a[0][3], aoff[0] + kb);
                LDSM_X4(a[1][0], a[1][1], a[1][2], a[1][3], aoff[1] + kb);
                LDSM_X4(b[0][0], b[0][1], b[0][2], b[0][3], bufc + boff[0] + kb);
                LDSM_X4(b[1][0], b[1][1], b[1][2], b[1][3], bufc + boff[1] + kb);
                #pragma unroll
                for (int m = 0; m < 2; m++)
                    #pragma unroll
                    for (int nb = 0; nb < 2; nb++) {
                        MMAS8(acc[m][nb*2+0], a[m][0], a[m][1], a[m][2], a[m][3],
                              b[nb][0], b[nb][1]);
                        MMAS8(acc[m][nb*2+1], a[m][0], a[m][1], a[m][2], a[m][3],
                              b[nb][2], b[nb][3]);
                    }
            }

            // ---- epilogue ----
            const bool isDiag = (I == J);
            const bool isPos  = (J == I + BHALF / CT);
            const int colb = J * CT;
            float cs[8];
            #pragma unroll
            for (int k = 0; k < 8; k++) cs[k] = 0.0f;

            if (!isDiag && !isPos) {
                // FAST PATH: no indices, no predicates.
                #pragma unroll
                for (int m = 0; m < 2; m++)
                    #pragma unroll
                    for (int n = 0; n < 4; n++)
                        #pragma unroll
                        for (int c = 0; c < 4; c++) {
                            float e = ex2f(fmaf(__int_as_float(acc[m][n][c]), KQ, BQ));
                            rs[m][c >> 1]        += e;   // row partial
                            cs[n * 2 + (c & 1)]  += e;   // column partial
                        }
            } else {
                const int rowb = I * MT;
                #pragma unroll
                for (int m = 0; m < 2; m++) {
                    #pragma unroll
                    for (int n = 0; n < 4; n++) {
                        #pragma unroll
                        for (int c = 0; c < 4; c++) {
                            float f = __int_as_float(acc[m][n][c]);
                            float e = ex2f(fmaf(f, KQ, BQ));
                            int gr = rowb + wm * 32 + m * 16 + ((c >> 1) << 3) + l4;
                            int gc = colb + wn * 32 + n * 8 + lm * 2 + (c & 1);
                            if (isDiag) {
                                if (gc == gr) e = 0.0f;          // mask self-sim
                            } else {
                                if (gc == gr + BHALF) {          // positive pair
                                    float pv = fmaf(f, KP, BP);  // sim = cos/T
                                    g_pos[gr] = pv;
                                    g_pos[gc] = pv;
                                }
                                cs[n * 2 + (c & 1)] += e;
                            }
                            rs[m][c >> 1] += e;
                        }
                    }
                }
            }

            if (!isDiag) {
                // reduce col partials over the 8 l4-lanes, then REDG
                #pragma unroll
                for (int k = 0; k < 8; k++) {
                    float v = cs[k];
                    v += __shfl_xor_sync(0xffffffffu, v, 4);
                    v += __shfl_xor_sync(0xffffffffu, v, 8);
                    v += __shfl_xor_sync(0xffffffffu, v, 16);
                    if (l4 == 0)
                        atomicAdd(&g_rowsum[colb + wn * 32 + (k >> 1) * 8
                                            + lm * 2 + (k & 1)], v);
                }
            }

            if (!haveNext) break;

            // A-switch: flush row sums for curI, reload A in place
            if (In != curI) {
                #pragma unroll
                for (int m = 0; m < 2; m++)
                    #pragma unroll
                    for (int h2 = 0; h2 < 2; h2++) {
                        float v = rs[m][h2];
                        v += __shfl_xor_sync(0xffffffffu, v, 1);
                        v += __shfl_xor_sync(0xffffffffu, v, 2);
                        if (lm == 0)
                            atomicAdd(&g_rowsum[curI * MT + wm * 32 + m * 16
                                                + h2 * 8 + l4], v);
                        rs[m][h2] = 0.0f;
                    }
                __syncthreads();           // all warps done reading old A
                curI = In;
                load_tile_async(sA, curI * MT);
                CP_COMMIT();               // joined by next iter's CP_WAIT(0)
            }
            u_cur = u_nxt;
            it++;
        }
    }

    // final row-sum flush
    if (worked) {
        #pragma unroll
        for (int m = 0; m < 2; m++)
            #pragma unroll
            for (int h2 = 0; h2 < 2; h2++) {
                float v = rs[m][h2];
                v += __shfl_xor_sync(0xffffffffu, v, 1);
                v += __shfl_xor_sync(0xffffffffu, v, 2);
                if (lm == 0)
                    atomicAdd(&g_rowsum[curI * MT + wm * 32 + m * 16 + h2 * 8 + l4], v);
            }
    }

    // ---- completion ticket: last CTA does the final reduction ----
    __threadfence();
    __syncthreads();
    if (tid == 0) s_last = atomicInc(&g_ticket, NCTA - 1u);
    __syncthreads();
    if (s_last == NCTA - 1u) {
        float acc = 0.0f;
        #pragma unroll
        for (int i = 0; i < 4; i++) {
            int r = (tid + i * THREADS) * 4;
            float4 s  = __ldcg((const float4*)(g_rowsum + r));
            float4 pp = __ldcg((const float4*)(g_pos + r));
            acc += (__logf(s.x) - pp.x) + (__logf(s.y) - pp.y)
                 + (__logf(s.z) - pp.z) + (__logf(s.w) - pp.w);
        }
        #pragma unroll
        for (int o = 16; o; o >>= 1) acc += __shfl_xor_sync(0xffffffffu, acc, o);
        if (lane == 0) red[warp] = acc;
        __syncthreads();
        if (tid == 0) {
            float v = 0.0f;
            #pragma unroll
            for (int w = 0; w < 16; w++) v += red[w];
            out[0] = v * (1.0f / NTOT);
        }
    }
}

// ---------------------------------------------------------------------------
extern "C" void kernel_launch(void* const* d_in, const int* in_sizes, int n_in,
                              void* d_out, int out_size) {
    const float* zi = (const float*)d_in[0];
    const float* zj = (const float*)d_in[1];
    float* out = (float*)d_out;

    const size_t smem = (size_t)TILE8 * 3;   // A + 2x B = 104,448 B (2 CTAs/SM)
    cudaFuncSetAttribute(k_main, cudaFuncAttributeMaxDynamicSharedMemorySize, (int)smem);

    k_prep<<<NTOT / 32, 256>>>(zi, zj);
    k_main<<<NCTA, THREADS, smem>>>(out);
}

// round 14
// speedup vs baseline: 1.1817x; 1.1817x over previous
#include <cuda_runtime.h>
#include <cuda_bf16.h>
#include <math.h>
#include <stdint.h>

#define NTOT   8192
#define BHALF  4096
#define DDIM   256
#define MT     128                  // rows per tile-block
#define CT     128                  // cols per tile
#define NRB    (NTOT / MT)          // 64 row-blocks
#define AS8    272                  // smem row stride bytes (256 data + 16 pad)
#define TILE8  (MT * AS8)           // 34816 bytes per tile buffer
#define NUNITS 2080                 // 32 strip-pairs x 65 tiles = all upper-tri tiles
#define NCTA   296                  // 2 CTAs x 148 SMs
#define THREADS 512

// Scratch: int8-quantized normalized vectors (q = round(127*zhat)),
// per-row sum-exp, per-row positive logit, completion ticket
__device__ int8_t g_q[NTOT * DDIM];
__device__ float g_rowsum[NTOT];
__device__ float g_pos[NTOT];
__device__ unsigned g_ticket;

// ---------------------------------------------------------------------------
__device__ __forceinline__ uint32_t smem_u32(const void* p) {
    uint32_t a;
    asm("{ .reg .u64 t; cvta.to.shared.u64 t, %1; cvt.u32.u64 %0, t; }"
        : "=r"(a) : "l"(p));
    return a;
}
__device__ __forceinline__ float ex2f(float x) {     // 2^x on MUFU pipe
    float r;
    asm("ex2.approx.f32 %0, %1;" : "=f"(r) : "f"(x));
    return r;
}
#define CP_ASYNC16(dst, src) \
    asm volatile("cp.async.cg.shared.global [%0], [%1], 16;" :: "r"(dst), "l"(src))
#define CP_COMMIT() asm volatile("cp.async.commit_group;" ::: "memory")
#define CP_WAIT(n)  asm volatile("cp.async.wait_group %0;" :: "n"(n) : "memory")

#define LDSM_X4(r0, r1, r2, r3, a)                                        \
    asm volatile("ldmatrix.sync.aligned.m8n8.x4.shared.b16 {%0,%1,%2,%3}, [%4];" \
        : "=r"(r0), "=r"(r1), "=r"(r2), "=r"(r3) : "r"(a))

#define MMAS8(d, a0, a1, a2, a3, b0, b1)                                  \
    asm volatile("mma.sync.aligned.m16n8k32.row.col.s32.s8.s8.s32 "       \
        "{%0,%1,%2,%3}, {%4,%5,%6,%7}, {%8,%9}, {%0,%1,%2,%3};"           \
        : "+r"((d)[0]), "+r"((d)[1]), "+r"((d)[2]), "+r"((d)[3])          \
        : "r"(a0), "r"(a1), "r"(a2), "r"(a3), "r"(b0), "r"(b1))

// First K-step: C operand is the broadcast MAGI constant -> no acc init MOVs.
#define MMAS8_INIT(d, a0, a1, a2, a3, b0, b1, c)                          \
    asm volatile("mma.sync.aligned.m16n8k32.row.col.s32.s8.s8.s32 "       \
        "{%0,%1,%2,%3}, {%4,%5,%6,%7}, {%8,%9}, {%10,%10,%10,%10};"       \
        : "=r"((d)[0]), "=r"((d)[1]), "=r"((d)[2]), "=r"((d)[3])          \
        : "r"(a0), "r"(a1), "r"(a2), "r"(a3), "r"(b0), "r"(b1), "r"(c))

// ---------------------------------------------------------------------------
// Prep: each warp handles 4 rows; also zeroes g_rowsum / g_ticket.
// ---------------------------------------------------------------------------
__device__ __forceinline__ const float* row_ptr(int row,
        const float* zi, const float* zj) {
    return (row < BHALF) ? (zi + (size_t)row * DDIM)
                         : (zj + (size_t)(row - BHALF) * DDIM);
}
__device__ __forceinline__ void quant_store(int row, float sc,
        float4 v0, float4 v1, int lane) {
    int q0 = __float2int_rn(v0.x * sc), q1 = __float2int_rn(v0.y * sc);
    int q2 = __float2int_rn(v0.z * sc), q3 = __float2int_rn(v0.w * sc);
    int q4 = __float2int_rn(v1.x * sc), q5 = __float2int_rn(v1.y * sc);
    int q6 = __float2int_rn(v1.z * sc), q7 = __float2int_rn(v1.w * sc);
    uint2 pk;
    pk.x = (q0 & 0xff) | ((q1 & 0xff) << 8) | ((q2 & 0xff) << 16) | (q3 << 24);
    pk.y = (q4 & 0xff) | ((q5 & 0xff) << 8) | ((q6 & 0xff) << 16) | (q7 << 24);
    *(uint2*)(g_q + (size_t)row * DDIM + lane * 8) = pk;
}

__global__ void k_prep(const float* __restrict__ zi, const float* __restrict__ zj) {
    if (blockIdx.x < 32) g_rowsum[blockIdx.x * 256 + threadIdx.x] = 0.0f;
    if (blockIdx.x == 0 && threadIdx.x == 0) g_ticket = 0u;

    const int warp = threadIdx.x >> 5;
    const int lane = threadIdx.x & 31;
    const int r0 = blockIdx.x * 32 + warp * 4;

    float4 v[8];
    #pragma unroll
    for (int r = 0; r < 4; r++) {
        const float* s = row_ptr(r0 + r, zi, zj);
        v[2*r]   = ((const float4*)s)[lane * 2 + 0];
        v[2*r+1] = ((const float4*)s)[lane * 2 + 1];
    }
    float ss[4];
    #pragma unroll
    for (int r = 0; r < 4; r++) {
        float4 a = v[2*r], b = v[2*r+1];
        ss[r] = a.x*a.x + a.y*a.y + a.z*a.z + a.w*a.w
              + b.x*b.x + b.y*b.y + b.z*b.z + b.w*b.w;
    }
    #pragma unroll
    for (int o = 16; o; o >>= 1)
        #pragma unroll
        for (int r = 0; r < 4; r++)
            ss[r] += __shfl_xor_sync(0xffffffffu, ss[r], o);
    #pragma unroll
    for (int r = 0; r < 4; r++)
        quant_store(r0 + r, 127.0f * rsqrtf(ss[r]), v[2*r], v[2*r+1], lane);
}

// ---------------------------------------------------------------------------
// Async tile loader: 128 rows x 256 int8; 2048 16B chunks over 512 threads.
// ---------------------------------------------------------------------------
__device__ __forceinline__ void load_tile_async(uint32_t dst, int grow0) {
    const int tid = threadIdx.x;
    #pragma unroll
    for (int i = 0; i < 4; i++) {
        int c   = tid + i * THREADS;
        int r   = c >> 4;
        int off = (c & 15) * 16;
        CP_ASYNC16(dst + r * AS8 + off,
                   (const char*)g_q + (size_t)(grow0 + r) * 256 + off);
    }
}

// Decode global unit u -> (I, J) on the strip-pair sweep (p = u/65, t = u%65).
__device__ __forceinline__ void decode_unit(unsigned u, int& I, int& J) {
    int p = (int)(u / 65u);
    int t = (int)(u - (unsigned)p * 65u);
    int len1 = NRB - p;                  // tiles in strip I=p (J=p..63)
    I = (t < len1) ? p : (NRB - 1 - p);
    J = (t < len1) ? (p + t) : ((NRB - 1 - p) + (t - len1));
}

// Static balanced split: S(b) = 7b + min(b,8). Blocks 0..7 take 8 units;
// their same-SM partners (b+148, classic bid%148->SM map) take 7 -> worst
// SM carries 15 units (vs 16 under the old per-strip chunking), mean 14.05.
__device__ __forceinline__ unsigned unit_start(int b) {
    int base = (b <= 148) ? b : (b - 148);
    unsigned s = 7u * (unsigned)base + (unsigned)min(base, 8);
    return (b <= 148) ? s : (1044u + 7u * (unsigned)(b - 148));
}

// ---------------------------------------------------------------------------
// Main: upper-triangle tile sweep with symmetry, int8 mma m16n8k32.
// R14 = R12 skeleton (single barrier per tile, 2-stage cp.async pipeline,
// fast/slow epilogue, REDG column sums) + balanced static unit ranges
// + const-C first MMA (no accumulator-init MOVs).
// ---------------------------------------------------------------------------
__global__ void __launch_bounds__(THREADS, 2) k_main(float* out) {
    extern __shared__ char sm[];
    __shared__ unsigned s_last;
    __shared__ float red[16];
    const uint32_t sA  = smem_u32(sm);
    const uint32_t sB0 = sA + TILE8;

    const int tid  = threadIdx.x;
    const int lane = tid & 31;
    const int warp = tid >> 5;
    const int wm   = warp & 3;             // M subtile (32 rows)
    const int wn   = warp >> 2;            // N subtile (32 cols), 0..3
    const int l4   = lane >> 2;
    const int lm   = lane & 3;

    const unsigned u0 = unit_start(blockIdx.x);
    const unsigned u1 = unit_start(blockIdx.x + 1);

    // ldmatrix per-lane base offsets (bytes); k-step adds ks*32
    uint32_t aoff[2];
    #pragma unroll
    for (int m = 0; m < 2; m++) {
        int arow = wm * 32 + m * 16 + (lane & 15);
        aoff[m] = sA + (uint32_t)arow * AS8 + (uint32_t)(lane >> 4) * 16;
    }
    uint32_t boff[2];
    #pragma unroll
    for (int nb = 0; nb < 2; nb++) {
        int brow = wn * 32 + nb * 16 + (lane & 7) + ((lane >> 4) << 3);
        boff[nb] = (uint32_t)brow * AS8 + (uint32_t)((lane >> 3) & 1) * 16;
    }

    #define BUF(u)  (sB0 + (uint32_t)(((u) - u0) & 1) * TILE8)

    // exp(cos/T) = 2^(dot_i32 * KQ);  KQ = log2(e)/(T*127^2)
    const float KQ   = 2.8853900817779268f / 16129.0f;
    const float KP   = 2.0f / 16129.0f;
    const float MAGF = 12582912.0f;               // 1.5 * 2^23
    const int   MAGI = 0x4B400000;
    const float BQ   = -MAGF * KQ;
    const float BP   = -MAGF * KP;
    float rs[2][2] = {{0.f, 0.f}, {0.f, 0.f}};

    int I0, J0;
    decode_unit(u0, I0, J0);
    int curI = I0;
    load_tile_async(sA, I0 * MT);
    load_tile_async(BUF(u0), J0 * CT);
    CP_COMMIT();

    for (unsigned u = u0; u < u1; u++) {
        int I, J;
        decode_unit(u, I, J);
        const uint32_t bufc = BUF(u);

        CP_WAIT(0);                       // B(u) (and A, after a switch) arrived
        __syncthreads();                  // publish B(u); retire reads of buf(u+1)
        int In = curI, Jn = 0;
        if (u + 1 < u1) {                 // prefetch B(u+1) (across switches too)
            decode_unit(u + 1, In, Jn);
            load_tile_async(BUF(u + 1), Jn * CT);
            CP_COMMIT();
        }

        // ---- mainloop: ks=0 seeds acc with MAGI via the C operand ----
        int acc[2][4][4];
        {
            uint32_t a[2][4], b[2][4];
            LDSM_X4(a[0][0], a[0][1], a[0][2], a[0][3], aoff[0]);
            LDSM_X4(a[1][0], a[1][1], a[1][2], a[1][3], aoff[1]);
            LDSM_X4(b[0][0], b[0][1], b[0][2], b[0][3], bufc + boff[0]);
            LDSM_X4(b[1][0], b[1][1], b[1][2], b[1][3], bufc + boff[1]);
            #pragma unroll
            for (int m = 0; m < 2; m++)
                #pragma unroll
                for (int nb = 0; nb < 2; nb++) {
                    MMAS8_INIT(acc[m][nb*2+0], a[m][0], a[m][1], a[m][2], a[m][3],
                               b[nb][0], b[nb][1], MAGI);
                    MMAS8_INIT(acc[m][nb*2+1], a[m][0], a[m][1], a[m][2], a[m][3],
                               b[nb][2], b[nb][3], MAGI);
                }
        }
        #pragma unroll
        for (int ks = 1; ks < 8; ks++) {
            const uint32_t kb = (uint32_t)ks * 32;
            uint32_t a[2][4], b[2][4];
            LDSM_X4(a[0][0], a[0][1], a[0][2], a[0][3], aoff[0] + kb);
            LDSM_X4(a[1][0], a[1][1], a[1][2], a[1][3], aoff[1] + kb);
            LDSM_X4(b[0][0], b[0][1], b[0][2], b[0][3], bufc + boff[0] + kb);
            LDSM_X4(b[1][0], b[1][1], b[1][2], b[1][3], bufc + boff[1] + kb);
            #pragma unroll
            for (int m = 0; m < 2; m++)
                #pragma unroll
                for (int nb = 0; nb < 2; nb++) {
                    MMAS8(acc[m][nb*2+0], a[m][0], a[m][1], a[m][2], a[m][3],
                          b[nb][0], b[nb][1]);
                    MMAS8(acc[m][nb*2+1], a[m][0], a[m][1], a[m][2], a[m][3],
                          b[nb][2], b[nb][3]);
                }
        }

        // ---- epilogue ----
        const bool isDiag = (I == J);
        const bool isPos  = (J == I + BHALF / CT);
        const int colb = J * CT;
        float cs[8];
        #pragma unroll
        for (int k = 0; k < 8; k++) cs[k] = 0.0f;

        if (!isDiag && !isPos) {
            // FAST PATH (~63/65 tiles): no indices, no predicates.
            #pragma unroll
            for (int m = 0; m < 2; m++)
                #pragma unroll
                for (int n = 0; n < 4; n++)
                    #pragma unroll
                    for (int c = 0; c < 4; c++) {
                        float e = ex2f(fmaf(__int_as_float(acc[m][n][c]), KQ, BQ));
                        rs[m][c >> 1]        += e;   // row partial
                        cs[n * 2 + (c & 1)]  += e;   // column partial (symmetry)
                    }
        } else {
            // SLOW PATH: diagonal tile (mask self-sim, no col contribution)
            // or positive tile (capture pos logits, col contribution kept).
            const int rowb = I * MT;
            #pragma unroll
            for (int m = 0; m < 2; m++) {
                #pragma unroll
                for (int n = 0; n < 4; n++) {
                    #pragma unroll
                    for (int c = 0; c < 4; c++) {
                        float f = __int_as_float(acc[m][n][c]);
                        float e = ex2f(fmaf(f, KQ, BQ));
                        int gr = rowb + wm * 32 + m * 16 + ((c >> 1) << 3) + l4;
                        int gc = colb + wn * 32 + n * 8 + lm * 2 + (c & 1);
                        if (isDiag) {
                            if (gc == gr) e = 0.0f;          // mask self-similarity
                        } else {
                            if (gc == gr + BHALF) {          // positive pair
                                float pv = fmaf(f, KP, BP);  // sim = cos/T
                                g_pos[gr] = pv;
                                g_pos[gc] = pv;              // symmetric partner
                            }
                            cs[n * 2 + (c & 1)] += e;
                        }
                        rs[m][c >> 1] += e;
                    }
                }
            }
        }

        if (!isDiag) {
            // reduce col partials over the 8 l4-lanes, then REDG to g_rowsum
            #pragma unroll
            for (int k = 0; k < 8; k++) {
                float v = cs[k];
                v += __shfl_xor_sync(0xffffffffu, v, 4);
                v += __shfl_xor_sync(0xffffffffu, v, 8);
                v += __shfl_xor_sync(0xffffffffu, v, 16);
                if (l4 == 0)
                    atomicAdd(&g_rowsum[colb + wn * 32 + (k >> 1) * 8 + lm * 2 + (k & 1)], v);
            }
        }

        // phase switch: flush row sums for curI, reload A in place.
        // (B(u+1) was already prefetched above; only A reloads here.)
        if (u + 1 < u1 && In != curI) {
            #pragma unroll
            for (int m = 0; m < 2; m++)
                #pragma unroll
                for (int h2 = 0; h2 < 2; h2++) {
                    float v = rs[m][h2];
                    v += __shfl_xor_sync(0xffffffffu, v, 1);
                    v += __shfl_xor_sync(0xffffffffu, v, 2);
                    if (lm == 0)
                        atomicAdd(&g_rowsum[curI * MT + wm * 32 + m * 16 + h2 * 8 + l4], v);
                    rs[m][h2] = 0.0f;
                }
            __syncthreads();              // all warps done reading old A
            curI = In;
            load_tile_async(sA, curI * MT);
            CP_COMMIT();                  // joined by next iter's CP_WAIT(0)
        }
    }

    // final row-sum flush
    #pragma unroll
    for (int m = 0; m < 2; m++)
        #pragma unroll
        for (int h2 = 0; h2 < 2; h2++) {
            float v = rs[m][h2];
            v += __shfl_xor_sync(0xffffffffu, v, 1);
            v += __shfl_xor_sync(0xffffffffu, v, 2);
            if (lm == 0)
                atomicAdd(&g_rowsum[curI * MT + wm * 32 + m * 16 + h2 * 8 + l4], v);
        }

    // ---- completion ticket: last CTA does the final reduction ----
    __threadfence();
    __syncthreads();
    if (tid == 0) s_last = atomicInc(&g_ticket, NCTA - 1u);  // 296th sees 295 -> wraps 0
    __syncthreads();
    if (s_last == NCTA - 1u) {
        float acc = 0.0f;
        #pragma unroll
        for (int i = 0; i < 4; i++) {
            int r = (tid + i * THREADS) * 4;
            float4 s  = __ldcg((const float4*)(g_rowsum + r));
            float4 pp = __ldcg((const float4*)(g_pos + r));
            acc += (__logf(s.x) - pp.x) + (__logf(s.y) - pp.y)
                 + (__logf(s.z) - pp.z) + (__logf(s.w) - pp.w);
        }
        #pragma unroll
        for (int o = 16; o; o >>= 1) acc += __shfl_xor_sync(0xffffffffu, acc, o);
        if (lane == 0) red[warp] = acc;
        __syncthreads();
        if (tid == 0) {
            float v = 0.0f;
            #pragma unroll
            for (int w = 0; w < 16; w++) v += red[w];
            out[0] = v * (1.0f / NTOT);
        }
    }
    #undef BUF
}

// ---------------------------------------------------------------------------
extern "C" void kernel_launch(void* const* d_in, const int* in_sizes, int n_in,
                              void* d_out, int out_size) {
    const float* zi = (const float*)d_in[0];
    const float* zj = (const float*)d_in[1];
    float* out = (float*)d_out;

    const size_t smem = (size_t)TILE8 * 3;   // A + 2x B = 104,448 B (2 CTAs/SM)
    cudaFuncSetAttribute(k_main, cudaFuncAttributeMaxDynamicSharedMemorySize, (int)smem);

    k_prep<<<NTOT / 32, 256>>>(zi, zj);
    k_main<<<NCTA, THREADS, smem>>>(out);
}

// round 15
// speedup vs baseline: 1.2481x; 1.0562x over previous
#include <cuda_runtime.h>
#include <cuda_bf16.h>
#include <math.h>
#include <stdint.h>

#define NTOT   8192
#define BHALF  4096
#define DDIM   256
#define MT     128                  // rows per tile-block
#define CT     128                  // cols per tile
#define NRB    (NTOT / MT)          // 64 row-blocks
#define AS8    272                  // smem row stride bytes (256 data + 16 pad)
#define TILE8  (MT * AS8)           // 34816 bytes per tile buffer
#define NUNITS 2080                 // 32 strip-pairs x 65 tiles = all upper-tri tiles
#define NCTA   296                  // 2 CTAs x 148 SMs
#define THREADS 512

// Scratch: int8-quantized normalized vectors (q = round(127*zhat)),
// per-row sum-exp, per-row positive logit, completion ticket
__device__ int8_t g_q[NTOT * DDIM];
__device__ float g_rowsum[NTOT];
__device__ float g_pos[NTOT];
__device__ unsigned g_ticket;

// ---------------------------------------------------------------------------
__device__ __forceinline__ uint32_t smem_u32(const void* p) {
    uint32_t a;
    asm("{ .reg .u64 t; cvta.to.shared.u64 t, %1; cvt.u32.u64 %0, t; }"
        : "=r"(a) : "l"(p));
    return a;
}
__device__ __forceinline__ float ex2f(float x) {     // 2^x on MUFU pipe
    float r;
    asm("ex2.approx.f32 %0, %1;" : "=f"(r) : "f"(x));
    return r;
}
#define CP_ASYNC16(dst, src) \
    asm volatile("cp.async.cg.shared.global [%0], [%1], 16;" :: "r"(dst), "l"(src))
#define CP_COMMIT() asm volatile("cp.async.commit_group;" ::: "memory")
#define CP_WAIT(n)  asm volatile("cp.async.wait_group %0;" :: "n"(n) : "memory")

#define LDSM_X4(r0, r1, r2, r3, a)                                        \
    asm volatile("ldmatrix.sync.aligned.m8n8.x4.shared.b16 {%0,%1,%2,%3}, [%4];" \
        : "=r"(r0), "=r"(r1), "=r"(r2), "=r"(r3) : "r"(a))

#define MMAS8(d, a0, a1, a2, a3, b0, b1)                                  \
    asm volatile("mma.sync.aligned.m16n8k32.row.col.s32.s8.s8.s32 "       \
        "{%0,%1,%2,%3}, {%4,%5,%6,%7}, {%8,%9}, {%0,%1,%2,%3};"           \
        : "+r"((d)[0]), "+r"((d)[1]), "+r"((d)[2]), "+r"((d)[3])          \
        : "r"(a0), "r"(a1), "r"(a2), "r"(a3), "r"(b0), "r"(b1))

// First K-step: C operand is the broadcast MAGI constant -> no acc init MOVs.
#define MMAS8_INIT(d, a0, a1, a2, a3, b0, b1, c)                          \
    asm volatile("mma.sync.aligned.m16n8k32.row.col.s32.s8.s8.s32 "       \
        "{%0,%1,%2,%3}, {%4,%5,%6,%7}, {%8,%9}, {%10,%10,%10,%10};"       \
        : "=r"((d)[0]), "=r"((d)[1]), "=r"((d)[2]), "=r"((d)[3])          \
        : "r"(a0), "r"(a1), "r"(a2), "r"(a3), "r"(b0), "r"(b1), "r"(c))

// ---------------------------------------------------------------------------
// Prep: each warp handles 4 rows; also zeroes g_rowsum / g_ticket.
// ---------------------------------------------------------------------------
__device__ __forceinline__ const float* row_ptr(int row,
        const float* zi, const float* zj) {
    return (row < BHALF) ? (zi + (size_t)row * DDIM)
                         : (zj + (size_t)(row - BHALF) * DDIM);
}
__device__ __forceinline__ void quant_store(int row, float sc,
        float4 v0, float4 v1, int lane) {
    int q0 = __float2int_rn(v0.x * sc), q1 = __float2int_rn(v0.y * sc);
    int q2 = __float2int_rn(v0.z * sc), q3 = __float2int_rn(v0.w * sc);
    int q4 = __float2int_rn(v1.x * sc), q5 = __float2int_rn(v1.y * sc);
    int q6 = __float2int_rn(v1.z * sc), q7 = __float2int_rn(v1.w * sc);
    uint2 pk;
    pk.x = (q0 & 0xff) | ((q1 & 0xff) << 8) | ((q2 & 0xff) << 16) | (q3 << 24);
    pk.y = (q4 & 0xff) | ((q5 & 0xff) << 8) | ((q6 & 0xff) << 16) | (q7 << 24);
    *(uint2*)(g_q + (size_t)row * DDIM + lane * 8) = pk;
}

__global__ void k_prep(const float* __restrict__ zi, const float* __restrict__ zj) {
    if (blockIdx.x < 32) g_rowsum[blockIdx.x * 256 + threadIdx.x] = 0.0f;
    if (blockIdx.x == 0 && threadIdx.x == 0) g_ticket = 0u;

    const int warp = threadIdx.x >> 5;
    const int lane = threadIdx.x & 31;
    const int r0 = blockIdx.x * 32 + warp * 4;

    float4 v[8];
    #pragma unroll
    for (int r = 0; r < 4; r++) {
        const float* s = row_ptr(r0 + r, zi, zj);
        v[2*r]   = ((const float4*)s)[lane * 2 + 0];
        v[2*r+1] = ((const float4*)s)[lane * 2 + 1];
    }
    float ss[4];
    #pragma unroll
    for (int r = 0; r < 4; r++) {
        float4 a = v[2*r], b = v[2*r+1];
        ss[r] = a.x*a.x + a.y*a.y + a.z*a.z + a.w*a.w
              + b.x*b.x + b.y*b.y + b.z*b.z + b.w*b.w;
    }
    #pragma unroll
    for (int o = 16; o; o >>= 1)
        #pragma unroll
        for (int r = 0; r < 4; r++)
            ss[r] += __shfl_xor_sync(0xffffffffu, ss[r], o);
    #pragma unroll
    for (int r = 0; r < 4; r++)
        quant_store(r0 + r, 127.0f * rsqrtf(ss[r]), v[2*r], v[2*r+1], lane);
}

// ---------------------------------------------------------------------------
// Async tile loader: 128 rows x 256 int8; 2048 16B chunks over 512 threads.
// ---------------------------------------------------------------------------
__device__ __forceinline__ void load_tile_async(uint32_t dst, int grow0) {
    const int tid = threadIdx.x;
    #pragma unroll
    for (int i = 0; i < 4; i++) {
        int c   = tid + i * THREADS;
        int r   = c >> 4;
        int off = (c & 15) * 16;
        CP_ASYNC16(dst + r * AS8 + off,
                   (const char*)g_q + (size_t)(grow0 + r) * 256 + off);
    }
}

// Decode global unit u -> (I, J) on the strip-pair sweep (p = u/65, t = u%65).
__device__ __forceinline__ void decode_unit(unsigned u, int& I, int& J) {
    int p = (int)(u / 65u);
    int t = (int)(u - (unsigned)p * 65u);
    int len1 = NRB - p;                  // tiles in strip I=p (J=p..63)
    I = (t < len1) ? p : (NRB - 1 - p);
    J = (t < len1) ? (p + t) : ((NRB - 1 - p) + (t - len1));
}

// Static balanced split: S(b) = 7b + min(b,8). Blocks 0..7 take 8 units;
// their same-SM partners (b+148) take 7 -> worst SM carries 15 units.
__device__ __forceinline__ unsigned unit_start(int b) {
    int base = (b <= 148) ? b : (b - 148);
    unsigned s = 7u * (unsigned)base + (unsigned)min(base, 8);
    return (b <= 148) ? s : (1044u + 7u * (unsigned)(b - 148));
}

// ---------------------------------------------------------------------------
// Main: upper-triangle tile sweep with symmetry, int8 mma m16n8k32.
// R15 = R14 + butterfly-ownership column reduction: 3 select/shfl/add stages
// leave lane l4 holding the full sum of cs[l4]; one coalesced 32-lane REDG
// replaces 24 SHFL + 24 FADD + 8 predicated REDG per warp per tile.
// ---------------------------------------------------------------------------
__global__ void __launch_bounds__(THREADS, 2) k_main(float* out) {
    extern __shared__ char sm[];
    __shared__ unsigned s_last;
    __shared__ float red[16];
    const uint32_t sA  = smem_u32(sm);
    const uint32_t sB0 = sA + TILE8;

    const int tid  = threadIdx.x;
    const int lane = tid & 31;
    const int warp = tid >> 5;
    const int wm   = warp & 3;             // M subtile (32 rows)
    const int wn   = warp >> 2;            // N subtile (32 cols), 0..3
    const int l4   = lane >> 2;
    const int lm   = lane & 3;

    const unsigned u0 = unit_start(blockIdx.x);
    const unsigned u1 = unit_start(blockIdx.x + 1);

    // ldmatrix per-lane base offsets (bytes); k-step adds ks*32
    uint32_t aoff[2];
    #pragma unroll
    for (int m = 0; m < 2; m++) {
        int arow = wm * 32 + m * 16 + (lane & 15);
        aoff[m] = sA + (uint32_t)arow * AS8 + (uint32_t)(lane >> 4) * 16;
    }
    uint32_t boff[2];
    #pragma unroll
    for (int nb = 0; nb < 2; nb++) {
        int brow = wn * 32 + nb * 16 + (lane & 7) + ((lane >> 4) << 3);
        boff[nb] = (uint32_t)brow * AS8 + (uint32_t)((lane >> 3) & 1) * 16;
    }

    // Butterfly ownership: after the 3-stage reduce, this lane holds the full
    // sum of cs[l4]; its REDG column within the warp's 32-col slice is:
    const int colRed = wn * 32 + (l4 >> 1) * 8 + lm * 2 + (l4 & 1);
    const bool hi0 = (l4 & 1), hi1 = (l4 & 2), hi2 = (l4 & 4);

    #define BUF(u)  (sB0 + (uint32_t)(((u) - u0) & 1) * TILE8)

    // exp(cos/T) = 2^(dot_i32 * KQ);  KQ = log2(e)/(T*127^2)
    const float KQ   = 2.8853900817779268f / 16129.0f;
    const float KP   = 2.0f / 16129.0f;
    const float MAGF = 12582912.0f;               // 1.5 * 2^23
    const int   MAGI = 0x4B400000;
    const float BQ   = -MAGF * KQ;
    const float BP   = -MAGF * KP;
    float rs[2][2] = {{0.f, 0.f}, {0.f, 0.f}};

    int I0, J0;
    decode_unit(u0, I0, J0);
    int curI = I0;
    load_tile_async(sA, I0 * MT);
    load_tile_async(BUF(u0), J0 * CT);
    CP_COMMIT();

    for (unsigned u = u0; u < u1; u++) {
        int I, J;
        decode_unit(u, I, J);
        const uint32_t bufc = BUF(u);

        CP_WAIT(0);                       // B(u) (and A, after a switch) arrived
        __syncthreads();                  // publish B(u); retire reads of buf(u+1)
        int In = curI, Jn = 0;
        if (u + 1 < u1) {                 // prefetch B(u+1) (across switches too)
            decode_unit(u + 1, In, Jn);
            load_tile_async(BUF(u + 1), Jn * CT);
            CP_COMMIT();
        }

        // ---- mainloop: ks=0 seeds acc with MAGI via the C operand ----
        int acc[2][4][4];
        {
            uint32_t a[2][4], b[2][4];
            LDSM_X4(a[0][0], a[0][1], a[0][2], a[0][3], aoff[0]);
            LDSM_X4(a[1][0], a[1][1], a[1][2], a[1][3], aoff[1]);
            LDSM_X4(b[0][0], b[0][1], b[0][2], b[0][3], bufc + boff[0]);
            LDSM_X4(b[1][0], b[1][1], b[1][2], b[1][3], bufc + boff[1]);
            #pragma unroll
            for (int m = 0; m < 2; m++)
                #pragma unroll
                for (int nb = 0; nb < 2; nb++) {
                    MMAS8_INIT(acc[m][nb*2+0], a[m][0], a[m][1], a[m][2], a[m][3],
                               b[nb][0], b[nb][1], MAGI);
                    MMAS8_INIT(acc[m][nb*2+1], a[m][0], a[m][1], a[m][2], a[m][3],
                               b[nb][2], b[nb][3], MAGI);
                }
        }
        #pragma unroll
        for (int ks = 1; ks < 8; ks++) {
            const uint32_t kb = (uint32_t)ks * 32;
            uint32_t a[2][4], b[2][4];
            LDSM_X4(a[0][0], a[0][1], a[0][2], a[0][3], aoff[0] + kb);
            LDSM_X4(a[1][0], a[1][1], a[1][2], a[1][3], aoff[1] + kb);
            LDSM_X4(b[0][0], b[0][1], b[0][2], b[0][3], bufc + boff[0] + kb);
            LDSM_X4(b[1][0], b[1][1], b[1][2], b[1][3], bufc + boff[1] + kb);
            #pragma unroll
            for (int m = 0; m < 2; m++)
                #pragma unroll
                for (int nb = 0; nb < 2; nb++) {
                    MMAS8(acc[m][nb*2+0], a[m][0], a[m][1], a[m][2], a[m][3],
                          b[nb][0], b[nb][1]);
                    MMAS8(acc[m][nb*2+1], a[m][0], a[m][1], a[m][2], a[m][3],
                          b[nb][2], b[nb][3]);
                }
        }

        // ---- epilogue ----
        const bool isDiag = (I == J);
        const bool isPos  = (J == I + BHALF / CT);
        const int colb = J * CT;
        float cs[8];
        #pragma unroll
        for (int k = 0; k < 8; k++) cs[k] = 0.0f;

        if (!isDiag && !isPos) {
            // FAST PATH (~63/65 tiles): no indices, no predicates.
            #pragma unroll
            for (int m = 0; m < 2; m++)
                #pragma unroll
                for (int n = 0; n < 4; n++)
                    #pragma unroll
                    for (int c = 0; c < 4; c++) {
                        float e = ex2f(fmaf(__int_as_float(acc[m][n][c]), KQ, BQ));
                        rs[m][c >> 1]        += e;   // row partial
                        cs[n * 2 + (c & 1)]  += e;   // column partial (symmetry)
                    }
        } else {
            // SLOW PATH: diagonal tile (mask self-sim, no col contribution)
            // or positive tile (capture pos logits, col contribution kept).
            const int rowb = I * MT;
            #pragma unroll
            for (int m = 0; m < 2; m++) {
                #pragma unroll
                for (int n = 0; n < 4; n++) {
                    #pragma unroll
                    for (int c = 0; c < 4; c++) {
                        float f = __int_as_float(acc[m][n][c]);
                        float e = ex2f(fmaf(f, KQ, BQ));
                        int gr = rowb + wm * 32 + m * 16 + ((c >> 1) << 3) + l4;
                        int gc = colb + wn * 32 + n * 8 + lm * 2 + (c & 1);
                        if (isDiag) {
                            if (gc == gr) e = 0.0f;          // mask self-similarity
                        } else {
                            if (gc == gr + BHALF) {          // positive pair
                                float pv = fmaf(f, KP, BP);  // sim = cos/T
                                g_pos[gr] = pv;
                                g_pos[gc] = pv;              // symmetric partner
                            }
                            cs[n * 2 + (c & 1)] += e;
                        }
                        rs[m][c >> 1] += e;
                    }
                }
            }
        }

        if (!isDiag) {
            // Butterfly-ownership reduce of cs[0..7] across the 8 l4-lanes.
            // Stage A (l4 bit0 <-> lane xor 4): 8 values -> 4
            float w[4];
            #pragma unroll
            for (int j = 0; j < 4; j++) {
                float snd = hi0 ? cs[2*j] : cs[2*j+1];
                float kp  = hi0 ? cs[2*j+1] : cs[2*j];
                w[j] = kp + __shfl_xor_sync(0xffffffffu, snd, 4);
            }
            // Stage B (l4 bit1 <-> lane xor 8): 4 -> 2
            float x[2];
            #pragma unroll
            for (int j = 0; j < 2; j++) {
                float snd = hi1 ? w[2*j] : w[2*j+1];
                float kp  = hi1 ? w[2*j+1] : w[2*j];
                x[j] = kp + __shfl_xor_sync(0xffffffffu, snd, 8);
            }
            // Stage C (l4 bit2 <-> lane xor 16): 2 -> 1; result = sum of cs[l4]
            {
                float snd = hi2 ? x[0] : x[1];
                float kp  = hi2 ? x[1] : x[0];
                float S = kp + __shfl_xor_sync(0xffffffffu, snd, 16);
                atomicAdd(&g_rowsum[colb + colRed], S);   // 32 lanes, coalesced
            }
        }

        // phase switch: flush row sums for curI, reload A in place.
        if (u + 1 < u1 && In != curI) {
            #pragma unroll
            for (int m = 0; m < 2; m++)
                #pragma unroll
                for (int h2 = 0; h2 < 2; h2++) {
                    float v = rs[m][h2];
                    v += __shfl_xor_sync(0xffffffffu, v, 1);
                    v += __shfl_xor_sync(0xffffffffu, v, 2);
                    if (lm == 0)
                        atomicAdd(&g_rowsum[curI * MT + wm * 32 + m * 16 + h2 * 8 + l4], v);
                    rs[m][h2] = 0.0f;
                }
            __syncthreads();              // all warps done reading old A
            curI = In;
            load_tile_async(sA, curI * MT);
            CP_COMMIT();                  // joined by next iter's CP_WAIT(0)
        }
    }

    // final row-sum flush
    #pragma unroll
    for (int m = 0; m < 2; m++)
        #pragma unroll
        for (int h2 = 0; h2 < 2; h2++) {
            float v = rs[m][h2];
            v += __shfl_xor_sync(0xffffffffu, v, 1);
            v += __shfl_xor_sync(0xffffffffu, v, 2);
            if (lm == 0)
                atomicAdd(&g_rowsum[curI * MT + wm * 32 + m * 16 + h2 * 8 + l4], v);
        }

    // ---- completion ticket: last CTA does the final reduction ----
    __threadfence();
    __syncthreads();
    if (tid == 0) s_last = atomicInc(&g_ticket, NCTA - 1u);  // 296th sees 295 -> wraps 0
    __syncthreads();
    if (s_last == NCTA - 1u) {
        float acc = 0.0f;
        #pragma unroll
        for (int i = 0; i < 4; i++) {
            int r = (tid + i * THREADS) * 4;
            float4 s  = __ldcg((const float4*)(g_rowsum + r));
            float4 pp = __ldcg((const float4*)(g_pos + r));
            acc += (__logf(s.x) - pp.x) + (__logf(s.y) - pp.y)
                 + (__logf(s.z) - pp.z) + (__logf(s.w) - pp.w);
        }
        #pragma unroll
        for (int o = 16; o; o >>= 1) acc += __shfl_xor_sync(0xffffffffu, acc, o);
        if (lane == 0) red[warp] = acc;
        __syncthreads();
        if (tid == 0) {
            float v = 0.0f;
            #pragma unroll
            for (int w = 0; w < 16; w++) v += red[w];
            out[0] = v * (1.0f / NTOT);
        }
    }
    #undef BUF
}

// ---------------------------------------------------------------------------
extern "C" void kernel_launch(void* const* d_in, const int* in_sizes, int n_in,
                              void* d_out, int out_size) {
    const float* zi = (const float*)d_in[0];
    const float* zj = (const float*)d_in[1];
    float* out = (float*)d_out;

    const size_t smem = (size_t)TILE8 * 3;   // A + 2x B = 104,448 B (2 CTAs/SM)
    cudaFuncSetAttribute(k_main, cudaFuncAttributeMaxDynamicSharedMemorySize, (int)smem);

    k_prep<<<NTOT / 32, 256>>>(zi, zj);
    k_main<<<NCTA, THREADS, smem>>>(out);
}